// round 4
// baseline (speedup 1.0000x reference)
#include <cuda_runtime.h>
#include <cstdint>

// Problem constants: B=2, N=65536, M=8192, K=32
// TOTAL_GIBS=64 (16 cy, 16 cone, 16 disk, 16 ellip), NUM_OBSERVERS=16
#define EPSV 1e-8f
#define LOG2E_F 1.4426950408889634f

constexpr int Bc = 2;
constexpr int Nc = 65536;
constexpr int Mc = 8192;
constexpr int Kc = 32;
constexpr int NQ = Bc * Mc;                 // 16384 queries
constexpr int WARPS_PER_BLOCK = 8;
constexpr int THREADS = WARPS_PER_BLOCK * 32;
constexpr int Q_PER_WARP = 4;               // 2 packed f32x2 pairs
constexpr int PAIRS = Q_PER_WARP / 2;
constexpr int Q_PER_BLOCK = WARPS_PER_BLOCK * Q_PER_WARP;   // 32
constexpr int GRID_BLOCKS = NQ / Q_PER_BLOCK;               // 512
constexpr int RPAD = 68;                    // padded row stride (words)

typedef unsigned long long u64;

__device__ __forceinline__ float ex2f(float x) {
    float r; asm("ex2.approx.ftz.f32 %0, %1;" : "=f"(r) : "f"(x)); return r;
}
__device__ __forceinline__ float sqrtaf(float x) {
    float r; asm("sqrt.approx.ftz.f32 %0, %1;" : "=f"(r) : "f"(x)); return r;
}
// ---- packed f32x2 helpers (Blackwell) ----
__device__ __forceinline__ u64 pk2(float lo, float hi) {
    u64 r; asm("mov.b64 %0, {%1, %2};" : "=l"(r) : "f"(lo), "f"(hi)); return r;
}
__device__ __forceinline__ void upk2(u64 v, float& lo, float& hi) {
    asm("mov.b64 {%0, %1}, %2;" : "=f"(lo), "=f"(hi) : "l"(v));
}
__device__ __forceinline__ u64 fma2(u64 a, u64 b, u64 c) {
    u64 d; asm("fma.rn.f32x2 %0, %1, %2, %3;" : "=l"(d) : "l"(a), "l"(b), "l"(c)); return d;
}
__device__ __forceinline__ u64 mul2(u64 a, u64 b) {
    u64 d; asm("mul.rn.f32x2 %0, %1, %2;" : "=l"(d) : "l"(a), "l"(b)); return d;
}

__global__ __launch_bounds__(THREADS, 4)
void gib_kernel(const float* __restrict__ points,
                const float* __restrict__ q_coords,
                const int*   __restrict__ support_idxs,
                const float* __restrict__ cy_p,
                const float* __restrict__ cone_p,
                const float* __restrict__ disk_p,
                const float* __restrict__ ellip_p,
                const float* __restrict__ lambdas,
                float* __restrict__ out)
{
    // pair-interleaved per-warp point data:
    //  sV[w][pair][view][k] = (u_A, u_B, rz_A, rz_B); view0: u=r2, view1: u=sqrt(r2+eps)
    //  sW[w][pair][k]       = (r2_A, r2_B, rx2_A, rx2_B)
    __shared__ float4 sV[WARPS_PER_BLOCK][PAIRS][2][Kc];   // 16 KB
    __shared__ float4 sW[WARPS_PER_BLOCK][PAIRS][Kc];      //  8 KB
    __shared__ float  lamT[16 * RPAD];                     // lamT[j][g] = lambdas[g][j]/K
    __shared__ float  meanS[Q_PER_BLOCK * RPAD];

    const int tid   = threadIdx.x;
    const int lane  = tid & 31;
    const int wslot = tid >> 5;
    const int qbase = blockIdx.x * Q_PER_BLOCK + wslot * Q_PER_WARP;

    // ---- cooperative transposed lambda load ----
    {
        const float invK = 1.f / (float)Kc;
        #pragma unroll
        for (int i = tid; i < 64 * 16; i += THREADS) {
            int g = i >> 4, j = i & 15;
            lamT[j * RPAD + g] = lambdas[i] * invK;
        }
    }

    // ---- per-lane gib constants, packed (same value in both halves) ----
    // quadratic (g0=lane): t = p1*u + p2*rz + p3 ; contrib = 2^(-t*t)
    // linear (g1=lane+32): a1 = q1p*rx2 + q2p*r2 + q3*rz2 ; contrib = 2^a1
    float p1, p2, p3, q1p, q2p, q3s;
    if (lane < 16) {
        float a  = cy_p[lane * 2 + 0];
        float sg = cy_p[lane * 2 + 1];
        float s0 = sqrtf(LOG2E_F / (2.f * sg * sg + EPSV));
        p1 = s0; p2 = 0.f; p3 = -s0 * a * a;
        float d0 = disk_p[lane * 2 + 0];
        float d1 = disk_p[lane * 2 + 1];
        q1p = 0.f;
        q2p = -LOG2E_F / (d0 * d0 + EPSV);
        q3s = -LOG2E_F / (d1 * d1 + EPSV);
    } else {
        int j = lane - 16;
        float a  = cone_p[j * 2 + 0];
        float sg = cone_p[j * 2 + 1];
        float s0 = sqrtf(LOG2E_F / (2.f * sg * sg + EPSV));
        p1 = s0; p2 = -s0 * a; p3 = 0.f;
        float e0 = ellip_p[j * 3 + 0];
        float e1 = ellip_p[j * 3 + 1];
        float e2 = ellip_p[j * 3 + 2];
        float qx = -LOG2E_F / (e0 * e0 + EPSV);
        float qy = -LOG2E_F / (e1 * e1 + EPSV);
        q1p = qx - qy;
        q2p = qy;
        q3s = -LOG2E_F / (e2 * e2 + EPSV);
    }
    const u64 P1 = pk2(p1, p1), P2 = pk2(p2, p2), P3 = pk2(p3, p3);
    const u64 Q1 = pk2(q1p, q1p), Q2 = pk2(q2p, q2p), Q3 = pk2(q3s, q3s);

    // ---- gather: lane k loads support point k for all 4 queries ----
    {
        float r2v[Q_PER_WARP], rzv[Q_PER_WARP], rx2v[Q_PER_WARP], sv[Q_PER_WARP];
        #pragma unroll
        for (int qq = 0; qq < Q_PER_WARP; qq++) {
            int q = qbase + qq;
            const float* qc = q_coords + q * 3;
            float qx = __ldg(qc + 0);
            float qy = __ldg(qc + 1);
            float qz = __ldg(qc + 2);
            int   idx = __ldg(support_idxs + q * Kc + lane);
            int   b   = q >> 13;                 // q / Mc
            const float* p = points + ((size_t)(b * Nc + idx)) * 3;
            float rx = __ldg(p + 0) - qx;
            float ry = __ldg(p + 1) - qy;
            float rz = __ldg(p + 2) - qz;
            float rx2 = rx * rx;
            float r2  = fmaf(ry, ry, rx2);
            r2v[qq] = r2; rzv[qq] = rz; rx2v[qq] = rx2;
            sv[qq]  = sqrtaf(r2 + EPSV);
        }
        #pragma unroll
        for (int p = 0; p < PAIRS; p++) {
            int a = 2 * p, b = 2 * p + 1;
            sV[wslot][p][0][lane] = make_float4(r2v[a], r2v[b], rzv[a], rzv[b]);
            sV[wslot][p][1][lane] = make_float4(sv[a],  sv[b],  rzv[a], rzv[b]);
            sW[wslot][p][lane]    = make_float4(r2v[a], r2v[b], rx2v[a], rx2v[b]);
        }
    }
    __syncwarp();

    const int half = lane >> 4;
    const float4* v0 = sV[wslot][0][half];
    const float4* v1 = sV[wslot][1][half];
    const float4* w0 = sW[wslot][0];
    const float4* w1 = sW[wslot][1];

    float acc0[Q_PER_WARP] = {0.f, 0.f, 0.f, 0.f};   // quadratic gib sums
    float acc1[Q_PER_WARP] = {0.f, 0.f, 0.f, 0.f};   // linear gib sums

    #pragma unroll
    for (int k = 0; k < Kc; k++) {
        // pair 0
        {
            float4 v = v0[k]; float4 w = w0[k];
            u64 up  = pk2(v.x, v.y);
            u64 rzp = pk2(v.z, v.w);
            u64 r2p = pk2(w.x, w.y);
            u64 rxp = pk2(w.z, w.w);
            u64 t   = fma2(P1, up, fma2(P2, rzp, P3));
            u64 z2  = mul2(rzp, rzp);
            u64 a1  = fma2(Q1, rxp, fma2(Q2, r2p, mul2(Q3, z2)));
            float tA, tB, aA, aB;
            upk2(t, tA, tB); upk2(a1, aA, aB);
            acc0[0] += ex2f(-tA * tA);
            acc0[1] += ex2f(-tB * tB);
            acc1[0] += ex2f(aA);
            acc1[1] += ex2f(aB);
        }
        // pair 1
        {
            float4 v = v1[k]; float4 w = w1[k];
            u64 up  = pk2(v.x, v.y);
            u64 rzp = pk2(v.z, v.w);
            u64 r2p = pk2(w.x, w.y);
            u64 rxp = pk2(w.z, w.w);
            u64 t   = fma2(P1, up, fma2(P2, rzp, P3));
            u64 z2  = mul2(rzp, rzp);
            u64 a1  = fma2(Q1, rxp, fma2(Q2, r2p, mul2(Q3, z2)));
            float tA, tB, aA, aB;
            upk2(t, tA, tB); upk2(a1, aA, aB);
            acc0[2] += ex2f(-tA * tA);
            acc0[3] += ex2f(-tB * tB);
            acc1[2] += ex2f(aA);
            acc1[3] += ex2f(aB);
        }
    }

    // publish the 64 gib means for the 4 queries
    #pragma unroll
    for (int qq = 0; qq < Q_PER_WARP; qq++) {
        int row = (wslot * Q_PER_WARP + qq) * RPAD;
        meanS[row + lane]      = acc0[qq];
        meanS[row + lane + 32] = acc1[qq];
    }
    __syncthreads();

    // ---- block-cooperative epilogue: 32 queries x 16 observers ----
    #pragma unroll
    for (int e = tid; e < Q_PER_BLOCK * 16; e += THREADS) {
        int qq = e >> 4;
        int j  = e & 15;
        const float4* mrow = reinterpret_cast<const float4*>(&meanS[qq * RPAD]);
        const float4* lrow = reinterpret_cast<const float4*>(&lamT[j * RPAD]);
        float acc = 0.f;
        #pragma unroll
        for (int g4 = 0; g4 < 16; g4++) {
            float4 m = mrow[g4];
            float4 l = lrow[g4];
            acc += m.x * l.x + m.y * l.y + m.z * l.z + m.w * l.w;
        }
        out[(size_t)(blockIdx.x * Q_PER_BLOCK + qq) * 16 + j] = acc;
    }
}

extern "C" void kernel_launch(void* const* d_in, const int* in_sizes, int n_in,
                              void* d_out, int out_size)
{
    // metadata order: points, q_coords, support_idxs, mc_points (unused),
    //                 cy_params, cone_params, disk_params, ellip_params, lambdas
    const float* points       = (const float*)d_in[0];
    const float* q_coords     = (const float*)d_in[1];
    const int*   support_idxs = (const int*)  d_in[2];
    const float* cy_params    = (const float*)d_in[4];
    const float* cone_params  = (const float*)d_in[5];
    const float* disk_params  = (const float*)d_in[6];
    const float* ellip_params = (const float*)d_in[7];
    const float* lambdas      = (const float*)d_in[8];
    float* out = (float*)d_out;

    gib_kernel<<<GRID_BLOCKS, THREADS>>>(points, q_coords, support_idxs,
                                         cy_params, cone_params, disk_params,
                                         ellip_params, lambdas, out);
}

// round 5
// speedup vs baseline: 1.0169x; 1.0169x over previous
#include <cuda_runtime.h>
#include <cstdint>

// Problem constants: B=2, N=65536, M=8192, K=32
// TOTAL_GIBS=64 (16 cy, 16 cone, 16 disk, 16 ellip), NUM_OBSERVERS=16
#define EPSV 1e-8f
#define LOG2E_F 1.4426950408889634f

constexpr int Bc = 2;
constexpr int Nc = 65536;
constexpr int Mc = 8192;
constexpr int Kc = 32;
constexpr int NQ = Bc * Mc;                 // 16384 queries
constexpr int WARPS_PER_BLOCK = 8;
constexpr int THREADS = WARPS_PER_BLOCK * 32;
constexpr int Q_PER_WARP = 2;
constexpr int Q_PER_BLOCK = WARPS_PER_BLOCK * Q_PER_WARP;   // 16
constexpr int GRID_BLOCKS = NQ / Q_PER_BLOCK;               // 1024
constexpr int RPAD = 68;                    // padded row stride (words)

__device__ __forceinline__ float ex2f(float x) {
    float r; asm("ex2.approx.ftz.f32 %0, %1;" : "=f"(r) : "f"(x)); return r;
}
__device__ __forceinline__ float sqrtaf(float x) {
    float r; asm("sqrt.approx.ftz.f32 %0, %1;" : "=f"(r) : "f"(x)); return r;
}

__global__ __launch_bounds__(THREADS, 4)
void gib_kernel(const float* __restrict__ points,
                const float* __restrict__ q_coords,
                const int*   __restrict__ support_idxs,
                const float* __restrict__ cy_p,
                const float* __restrict__ cone_p,
                const float* __restrict__ disk_p,
                const float* __restrict__ ellip_p,
                const float* __restrict__ lambdas,
                float* __restrict__ out)
{
    // per-warp, per-query monomial data, 2 half-warp views:
    //   view0 (lanes 0-15, cyl+disk):  (r4, r2, rz2, r2)
    //   view1 (lanes 16-31, cone+ell): (r2, srz, rz2, rx2)
    __shared__ float4 sPts[WARPS_PER_BLOCK][Q_PER_WARP][2][Kc];   // 16 KB
    __shared__ float  lamT[16 * RPAD];           // lamT[j][g] = lambdas[g][j]/K
    __shared__ float  meanS[Q_PER_BLOCK * RPAD]; // meanS[qq][g]

    const int tid   = threadIdx.x;
    const int lane  = tid & 31;
    const int wslot = tid >> 5;
    const int qbase = blockIdx.x * Q_PER_BLOCK;
    const int qA    = qbase + wslot * 2;

    // ---- cooperative transposed lambda load (once per block) ----
    {
        const float invK = 1.f / (float)Kc;
        #pragma unroll
        for (int i = tid; i < 64 * 16; i += THREADS) {
            int g = i >> 4, j = i & 15;
            lamT[j * RPAD + g] = lambdas[i] * invK;
        }
    }

    // ---- per-lane gib constants: fully uniform affine forms ----
    // quad gib (g0=lane):  arg0 = c1*v.x + c2*v.y + c3*v.z + c0
    // lin  gib (g1=l+32):  arg1 = e1*v.w + e2*v.x + e3*v.z
    float c0, c1, c2, c3, e1, e2, e3;
    if (lane < 16) {
        // cylinder: -(r2-a^2)^2*inv = -inv*r4 + 2a^2*inv*r2 - a^4*inv
        float a  = cy_p[lane * 2 + 0];
        float sg = cy_p[lane * 2 + 1];
        float inv = LOG2E_F / (2.f * sg * sg + EPSV);
        float a2 = a * a;
        c1 = -inv;
        c2 = 2.f * a2 * inv;
        c3 = 0.f;
        c0 = -a2 * a2 * inv;
        // disk: e1 on r2 (v.w), e3 on rz2 (v.z)
        float d0 = disk_p[lane * 2 + 0];
        float d1 = disk_p[lane * 2 + 1];
        e1 = -LOG2E_F / (d0 * d0 + EPSV);
        e2 = 0.f;
        e3 = -LOG2E_F / (d1 * d1 + EPSV);
    } else {
        // cone: -(s-a*rz)^2*inv, s^2 = r2+EPS exactly:
        //   = -inv*r2 + 2a*inv*srz - a^2*inv*rz2 - inv*EPS
        int j = lane - 16;
        float a  = cone_p[j * 2 + 0];
        float sg = cone_p[j * 2 + 1];
        float inv = LOG2E_F / (2.f * sg * sg + EPSV);
        c1 = -inv;
        c2 = 2.f * a * inv;
        c3 = -a * a * inv;
        c0 = -EPSV * inv;
        // ellip: qx*rx2 + qy*ry2 + qz*rz2 = (qx-qy)*rx2 + qy*r2 + qz*rz2
        float x0 = ellip_p[j * 3 + 0];
        float x1 = ellip_p[j * 3 + 1];
        float x2 = ellip_p[j * 3 + 2];
        float qx = -LOG2E_F / (x0 * x0 + EPSV);
        float qy = -LOG2E_F / (x1 * x1 + EPSV);
        float qz = -LOG2E_F / (x2 * x2 + EPSV);
        e1 = qx - qy;   // on rx2 (v.w)
        e2 = qy;        // on r2  (v.x)
        e3 = qz;        // on rz2 (v.z)
    }

    // ---- gather: lane k loads support point k for both queries ----
    #pragma unroll
    for (int qq = 0; qq < Q_PER_WARP; qq++) {
        int q = qA + qq;
        const float* qc = q_coords + q * 3;
        float qx = __ldg(qc + 0);
        float qy = __ldg(qc + 1);
        float qz = __ldg(qc + 2);
        int   idx = __ldg(support_idxs + q * Kc + lane);
        int   b   = q >> 13;                 // q / Mc
        const float* p = points + ((size_t)(b * Nc + idx)) * 3;
        float rx = __ldg(p + 0) - qx;
        float ry = __ldg(p + 1) - qy;
        float rz = __ldg(p + 2) - qz;
        float rx2 = rx * rx;
        float r2  = fmaf(ry, ry, rx2);
        float rz2 = rz * rz;
        float r4  = r2 * r2;
        float s   = sqrtaf(r2 + EPSV);
        float srz = s * rz;
        sPts[wslot][qq][0][lane] = make_float4(r4, r2,  rz2, r2);
        sPts[wslot][qq][1][lane] = make_float4(r2, srz, rz2, rx2);
    }
    __syncwarp();

    const int half = lane >> 4;
    const float4* vA = sPts[wslot][0][half];
    const float4* vB = sPts[wslot][1][half];

    float acc0A = 0.f, acc1A = 0.f, acc0B = 0.f, acc1B = 0.f;
    #pragma unroll
    for (int k = 0; k < Kc; k++) {
        float4 a = vA[k];                    // LDS.128 broadcast (2 addr groups)
        float4 b = vB[k];

        float arg0A = fmaf(c1, a.x, fmaf(c2, a.y, fmaf(c3, a.z, c0)));
        float arg0B = fmaf(c1, b.x, fmaf(c2, b.y, fmaf(c3, b.z, c0)));
        float arg1A = fmaf(e1, a.w, fmaf(e2, a.x, e3 * a.z));
        float arg1B = fmaf(e1, b.w, fmaf(e2, b.x, e3 * b.z));

        acc0A += ex2f(arg0A);
        acc0B += ex2f(arg0B);
        acc1A += ex2f(arg1A);
        acc1B += ex2f(arg1B);
    }

    // publish the 64 gib means for both queries
    {
        int qqA = wslot * 2, qqB = qqA + 1;
        meanS[qqA * RPAD + lane]      = acc0A;
        meanS[qqA * RPAD + lane + 32] = acc1A;
        meanS[qqB * RPAD + lane]      = acc0B;
        meanS[qqB * RPAD + lane + 32] = acc1B;
    }
    __syncthreads();

    // ---- block-cooperative epilogue: 16 queries x 16 observers ----
    {
        int qq = tid >> 4;
        int j  = tid & 15;
        const float4* mrow = reinterpret_cast<const float4*>(&meanS[qq * RPAD]);
        const float4* lrow = reinterpret_cast<const float4*>(&lamT[j * RPAD]);
        float acc = 0.f;
        #pragma unroll
        for (int g4 = 0; g4 < 16; g4++) {
            float4 m = mrow[g4];
            float4 l = lrow[g4];
            acc += m.x * l.x + m.y * l.y + m.z * l.z + m.w * l.w;
        }
        out[(size_t)(qbase + qq) * 16 + j] = acc;   // fully coalesced
    }
}

extern "C" void kernel_launch(void* const* d_in, const int* in_sizes, int n_in,
                              void* d_out, int out_size)
{
    // metadata order: points, q_coords, support_idxs, mc_points (unused),
    //                 cy_params, cone_params, disk_params, ellip_params, lambdas
    const float* points       = (const float*)d_in[0];
    const float* q_coords     = (const float*)d_in[1];
    const int*   support_idxs = (const int*)  d_in[2];
    const float* cy_params    = (const float*)d_in[4];
    const float* cone_params  = (const float*)d_in[5];
    const float* disk_params  = (const float*)d_in[6];
    const float* ellip_params = (const float*)d_in[7];
    const float* lambdas      = (const float*)d_in[8];
    float* out = (float*)d_out;

    gib_kernel<<<GRID_BLOCKS, THREADS>>>(points, q_coords, support_idxs,
                                         cy_params, cone_params, disk_params,
                                         ellip_params, lambdas, out);
}